// round 6
// baseline (speedup 1.0000x reference)
#include <cuda_runtime.h>
#include <cstdint>

#define BATCH   16
#define CHX     256
#define NPOS    170
#define TT      64
#define CIN     512
#define COUT    512
#define NHEAD   8
#define HDIM    64
#define BN      (BATCH*NPOS)      // 2720
#define TOKENS  (BN*TT)           // 174080
#define NTSTR   (NPOS*TT)         // 10880
#define QKV_ELEMS (BN*NHEAD*TT*HDIM)   // 89,128,960

// Scratch (device globals — no allocation allowed). All hold tf32 bit patterns.
__device__ float g_x[CIN*TOKENS];      // [c][token, sigma-permuted per 32-block]
__device__ float g_w[4*512*512];       // [mat(q,k,v,o)][n][ktile][rho-permuted k]
__device__ float g_q[QKV_ELEMS];       // [(bn*8+h)][t][dd]
__device__ float g_k[QKV_ELEMS];
__device__ float g_v[QKV_ELEMS];
__device__ float g_o2[CIN*TOKENS];     // [c][token, sigma-permuted]  (attention out)

// ---------------------------------------------------------------------------
__device__ __forceinline__ uint32_t f2tf32(float f) {
    uint32_t r;
    asm("cvt.rna.tf32.f32 %0, %1;" : "=r"(r) : "f"(f));
    return r;
}

__device__ __forceinline__ void mma_tf32(float* d, const uint32_t* a, const uint32_t* b) {
    asm volatile(
        "mma.sync.aligned.m16n8k8.row.col.f32.tf32.tf32.f32 "
        "{%0,%1,%2,%3},{%4,%5,%6,%7},{%8,%9},{%0,%1,%2,%3};\n"
        : "+f"(d[0]), "+f"(d[1]), "+f"(d[2]), "+f"(d[3])
        : "r"(a[0]), "r"(a[1]), "r"(a[2]), "r"(a[3]),
          "r"(b[0]), "r"(b[1]));
}

__device__ __forceinline__ void cpasync16(float* smem_dst, const float* gsrc) {
    uint32_t s = (uint32_t)__cvta_generic_to_shared(smem_dst);
    asm volatile("cp.async.cg.shared.global [%0], [%1], 16;\n"
                 :: "r"(s), "l"(gsrc) : "memory");
}
#define CP_COMMIT() asm volatile("cp.async.commit_group;\n" ::: "memory")
#define CP_WAIT2()  asm volatile("cp.async.wait_group 2;\n" ::: "memory")

// ---------------------------------------------------------------------------
// Prepass 1: x||tem -> g_x (tf32, sigma-permuted tokens).
// sigma(t) = (t&7)*4 + (t>>3) within each 32-token block.
// grid 8192 (= c*16 + b), block 256.
// ---------------------------------------------------------------------------
__global__ void cvt_x_kernel(const float* __restrict__ x, const float* __restrict__ tem)
{
    const int cb = blockIdx.x;
    const int c = cb >> 4, b = cb & 15;
    const float* src = (c < CHX) ? (x + (size_t)(b * CHX + c) * NTSTR)
                                 : (tem + (size_t)(b * CHX + c - CHX) * NTSTR);
    uint32_t* dst = (uint32_t*)g_x + (size_t)c * TOKENS + b * NTSTR;

    for (int m = threadIdx.x; m < NTSTR / 4; m += 256) {
        int u = 4 * m;
        int blk = u & ~31, m8 = m & 7;
        uint4 o;
        o.x = f2tf32(__ldg(&src[blk + m8]));
        o.y = f2tf32(__ldg(&src[blk + m8 + 8]));
        o.z = f2tf32(__ldg(&src[blk + m8 + 16]));
        o.w = f2tf32(__ldg(&src[blk + m8 + 24]));
        *(uint4*)(dst + u) = o;
    }
}

// ---------------------------------------------------------------------------
// Prepass 2: weights -> g_w tf32, k rho-permuted per 32-k tile.
// stored[r] holds original k = kt*32 + (r&7)*4 + (r>>3).
// 1,048,576 elements -> grid 4096, block 256.  (R4 bug: grid was 1024.)
// ---------------------------------------------------------------------------
__global__ void cvt_w_kernel(const float* __restrict__ Wq, const float* __restrict__ Wk,
                             const float* __restrict__ Wv, const float* __restrict__ Wo)
{
    int e = blockIdx.x * 256 + threadIdx.x;          // 0 .. 1M-1
    int mat = e >> 18;
    int rem = e & ((1 << 18) - 1);
    int n  = rem >> 9;
    int kt = (rem >> 5) & 15;
    int r  = rem & 31;
    int k  = kt * 32 + (r & 7) * 4 + (r >> 3);
    const float* W = (mat == 0) ? Wq : (mat == 1) ? Wk : (mat == 2) ? Wv : Wo;
    ((uint32_t*)g_w)[e] = f2tf32(__ldg(&W[n * 512 + k]));
}

// ---------------------------------------------------------------------------
// Shared GEMM mainloop tile: A [32 k][128 tok-sigma] stride 136,
// B [128 n][32 k-rho] stride 36. All tf32 bits. 88 issues per warp per ktile.
// ---------------------------------------------------------------------------
#define SA 136
#define SB 36
#define AW (32*SA)            // 4352 words
#define BW (128*SB)           // 4608 words
#define STAGE (AW+BW)         // 8960 words
#define SMEM_BYTES (3*STAGE*4)   // 107520

__device__ __forceinline__ void mma_ktile(const float* As, const float* Bs,
                                          float (&acc)[2][8][4],
                                          int mbase, int nbase, int g, int t4)
{
#pragma unroll
    for (int h = 0; h < 2; h++) {
        uint4 a0 = *(const uint4*)(As + (h*16 + t4     ) * SA + mbase + 4*g);
        uint4 a1 = *(const uint4*)(As + (h*16 + t4 + 4 ) * SA + mbase + 4*g);
        uint4 a2 = *(const uint4*)(As + (h*16 + t4 + 8 ) * SA + mbase + 4*g);
        uint4 a3 = *(const uint4*)(As + (h*16 + t4 + 12) * SA + mbase + 4*g);
        uint32_t af0[2][4] = {{a0.x, a0.y, a1.x, a1.y}, {a0.z, a0.w, a1.z, a1.w}};
        uint32_t af1[2][4] = {{a2.x, a2.y, a3.x, a3.y}, {a2.z, a2.w, a3.z, a3.w}};
#pragma unroll
        for (int ni = 0; ni < 8; ni++) {
            int c = nbase + ni * 8 + g;
            uint4 bv = *(const uint4*)(Bs + c * SB + t4 * 8 + h * 4);
            uint32_t bf0[2] = {bv.x, bv.y};
            uint32_t bf1[2] = {bv.z, bv.w};
            mma_tf32(acc[0][ni], af0[0], bf0);
            mma_tf32(acc[1][ni], af0[1], bf0);
            mma_tf32(acc[0][ni], af1[0], bf1);
            mma_tf32(acc[1][ni], af1[1], bf1);
        }
    }
}

// ---------------------------------------------------------------------------
// Kernel 1: QKV projection. grid (12, 1360): x = variant (L2 reuse of A), y = bn-pair.
// ---------------------------------------------------------------------------
__global__ __launch_bounds__(256, 2)
void qkv_kernel(const float* __restrict__ bq, const float* __restrict__ bk,
                const float* __restrict__ bv)
{
    extern __shared__ float sm[];

    const int tid = threadIdx.x;
    const int bn0 = blockIdx.y * 2;
    const int y   = blockIdx.x;
    const int mat = y >> 2;             // 0:q 1:k 2:v
    const int r0  = (y & 3) * 128;

    const float* bias;  float* outBuf;
    if (mat == 0)      { bias = bq; outBuf = g_q; }
    else if (mat == 1) { bias = bk; outBuf = g_k; }
    else               { bias = bv; outBuf = g_v; }

    // cp.async chunk metadata
    int kA[4], tcA[4], dstA[4], gB[4], dstB[4];
#pragma unroll
    for (int j = 0; j < 4; j++) {
        int cidx = tid + j * 256;
        kA[j]  = cidx >> 5;
        int tc = cidx & 31;
        tcA[j] = bn0 * 64 + tc * 4;
        dstA[j] = kA[j] * SA + tc * 4;
        int nn = cidx >> 3, kc = cidx & 7;
        gB[j]   = ((mat * 512 + r0 + nn) * 16) * 32 + kc * 4;   // + kt*32 later
        dstB[j] = nn * SB + kc * 4;
    }

    const int lane = tid & 31, wid = tid >> 5;
    const int wm = wid & 3, wn = wid >> 2;
    const int g = lane >> 2, t4 = lane & 3;
    const int mbase = wm * 32, nbase = wn * 64;

    float acc[2][8][4];
#pragma unroll
    for (int mi = 0; mi < 2; mi++)
#pragma unroll
        for (int ni = 0; ni < 8; ni++)
#pragma unroll
            for (int j = 0; j < 4; j++) acc[mi][ni][j] = 0.f;

    auto issue = [&](int stage, int kt) {
        float* As = sm + stage * STAGE;
        float* Bs = As + AW;
#pragma unroll
        for (int j = 0; j < 4; j++)
            cpasync16(As + dstA[j], g_x + (kt * 32 + kA[j]) * TOKENS + tcA[j]);
#pragma unroll
        for (int j = 0; j < 4; j++)
            cpasync16(Bs + dstB[j], g_w + gB[j] + kt * 32);
    };

#pragma unroll
    for (int s = 0; s < 3; s++) { issue(s, s); CP_COMMIT(); }

    for (int it = 0; it < 16; it++) {
        CP_WAIT2();
        __syncthreads();
        const int buf = it % 3;
        const float* As = sm + buf * STAGE;
        const float* Bs = As + AW;
        mma_ktile(As, Bs, acc, mbase, nbase, g, t4);
        __syncthreads();
        int nx = it + 3;
        if (nx < 16) issue(buf, nx);
        CP_COMMIT();
    }

    // Epilogue: bias + store tf32 bits into per-head [T,d] tiles
    uint32_t* ob32 = (uint32_t*)outBuf;
#pragma unroll
    for (int mi = 0; mi < 2; mi++) {
        int rloc = mbase + mi * 16 + g;          // acc rows == original tokens
        int bn = bn0 + (rloc >> 6);
        int t  = rloc & 63;
        int tileBase = (bn * NHEAD) * (TT * HDIM);
#pragma unroll
        for (int ni = 0; ni < 8; ni++) {
            int jj = nbase + ni * 8 + 2 * t4;
            int o = r0 + jj;
            int h = o >> 6, dd = o & 63;
            float b0 = bias[o], b1 = bias[o + 1];
            uint2 v0 = make_uint2(f2tf32(acc[mi][ni][0] + b0), f2tf32(acc[mi][ni][1] + b1));
            uint2 v1 = make_uint2(f2tf32(acc[mi][ni][2] + b0), f2tf32(acc[mi][ni][3] + b1));
            int base = tileBase + h * (TT * HDIM) + dd;
            *(uint2*)&ob32[base + t * HDIM]       = v0;
            *(uint2*)&ob32[base + (t + 8) * HDIM] = v1;
        }
    }
}

// ---------------------------------------------------------------------------
// Kernel 2: causal attention per (bn, head) tile. Inputs already tf32 bits.
// Epilogue transposes O into g_o2 [c][token-sigma] (tf32 bits).
// ---------------------------------------------------------------------------
__global__ __launch_bounds__(128, 4)
void attn_kernel()
{
    __shared__ uint32_t Qs[64 * 68];   // Q, then P
    __shared__ uint32_t Ks[64 * 68];   // K, then V^T, then O^T

    const int tid = threadIdx.x;
    const int lane = tid & 31, wid = tid >> 5;
    const int g = lane >> 2, t4 = lane & 3;
    const int bh = blockIdx.x;
    const int base = bh * (TT * HDIM);

    const uint32_t* gq = (const uint32_t*)g_q;
    const uint32_t* gk = (const uint32_t*)g_k;
    const uint32_t* gv = (const uint32_t*)g_v;

#pragma unroll
    for (int i = tid * 4; i < TT * HDIM; i += 512) {
        int t = i >> 6, d = i & 63;
        *(uint4*)&Qs[t * 68 + d] = *(const uint4*)(gq + base + i);
        *(uint4*)&Ks[t * 68 + d] = *(const uint4*)(gk + base + i);
    }
    __syncthreads();

    const int rbase = wid * 16;
    float s[8][4];
#pragma unroll
    for (int ni = 0; ni < 8; ni++)
#pragma unroll
        for (int j = 0; j < 4; j++) s[ni][j] = 0.f;

#pragma unroll
    for (int ks = 0; ks < 64; ks += 8) {
        uint32_t af[4];
        int r = rbase + g;
        af[0] = Qs[r * 68 + ks + t4];
        af[1] = Qs[(r + 8) * 68 + ks + t4];
        af[2] = Qs[r * 68 + ks + t4 + 4];
        af[3] = Qs[(r + 8) * 68 + ks + t4 + 4];
#pragma unroll
        for (int ni = 0; ni < 8; ni++) {
            uint32_t bf[2];
            bf[0] = Ks[(ni * 8 + g) * 68 + ks + t4];
            bf[1] = Ks[(ni * 8 + g) * 68 + ks + t4 + 4];
            mma_tf32(s[ni], af, bf);
        }
    }
    __syncthreads();

    const int rA = rbase + g, rB = rA + 8;
    float mx0 = -1e30f, mx1 = -1e30f;
#pragma unroll
    for (int ni = 0; ni < 8; ni++) {
        int c0 = ni * 8 + 2 * t4, c1 = c0 + 1;
        s[ni][0] = (c0 <= rA) ? s[ni][0] * 0.125f : -32767.0f;
        s[ni][1] = (c1 <= rA) ? s[ni][1] * 0.125f : -32767.0f;
        s[ni][2] = (c0 <= rB) ? s[ni][2] * 0.125f : -32767.0f;
        s[ni][3] = (c1 <= rB) ? s[ni][3] * 0.125f : -32767.0f;
        mx0 = fmaxf(mx0, fmaxf(s[ni][0], s[ni][1]));
        mx1 = fmaxf(mx1, fmaxf(s[ni][2], s[ni][3]));
    }
    mx0 = fmaxf(mx0, __shfl_xor_sync(0xffffffffu, mx0, 1));
    mx0 = fmaxf(mx0, __shfl_xor_sync(0xffffffffu, mx0, 2));
    mx1 = fmaxf(mx1, __shfl_xor_sync(0xffffffffu, mx1, 1));
    mx1 = fmaxf(mx1, __shfl_xor_sync(0xffffffffu, mx1, 2));

    float sm0 = 0.f, sm1 = 0.f;
#pragma unroll
    for (int ni = 0; ni < 8; ni++) {
        s[ni][0] = __expf(s[ni][0] - mx0); sm0 += s[ni][0];
        s[ni][1] = __expf(s[ni][1] - mx0); sm0 += s[ni][1];
        s[ni][2] = __expf(s[ni][2] - mx1); sm1 += s[ni][2];
        s[ni][3] = __expf(s[ni][3] - mx1); sm1 += s[ni][3];
    }
    sm0 += __shfl_xor_sync(0xffffffffu, sm0, 1);
    sm0 += __shfl_xor_sync(0xffffffffu, sm0, 2);
    sm1 += __shfl_xor_sync(0xffffffffu, sm1, 1);
    sm1 += __shfl_xor_sync(0xffffffffu, sm1, 2);
    float inv0 = 1.f / sm0, inv1 = 1.f / sm1;

#pragma unroll
    for (int ni = 0; ni < 8; ni++) {
        int c0 = ni * 8 + 2 * t4;
        Qs[rA * 68 + c0]     = f2tf32(s[ni][0] * inv0);
        Qs[rA * 68 + c0 + 1] = f2tf32(s[ni][1] * inv0);
        Qs[rB * 68 + c0]     = f2tf32(s[ni][2] * inv1);
        Qs[rB * 68 + c0 + 1] = f2tf32(s[ni][3] * inv1);
    }
    // V^T -> Ks
#pragma unroll
    for (int i = tid * 4; i < TT * HDIM; i += 512) {
        int t = i >> 6, d = i & 63;
        uint4 v4 = *(const uint4*)(gv + base + i);
        Ks[(d + 0) * 68 + t] = v4.x;
        Ks[(d + 1) * 68 + t] = v4.y;
        Ks[(d + 2) * 68 + t] = v4.z;
        Ks[(d + 3) * 68 + t] = v4.w;
    }
    __syncthreads();

    float o[8][4];
#pragma unroll
    for (int ni = 0; ni < 8; ni++)
#pragma unroll
        for (int j = 0; j < 4; j++) o[ni][j] = 0.f;

#pragma unroll
    for (int ks = 0; ks < 64; ks += 8) {
        uint32_t af[4];
        int r = rbase + g;
        af[0] = Qs[r * 68 + ks + t4];
        af[1] = Qs[(r + 8) * 68 + ks + t4];
        af[2] = Qs[r * 68 + ks + t4 + 4];
        af[3] = Qs[(r + 8) * 68 + ks + t4 + 4];
#pragma unroll
        for (int ni = 0; ni < 8; ni++) {
            uint32_t bf[2];
            bf[0] = Ks[(ni * 8 + g) * 68 + ks + t4];
            bf[1] = Ks[(ni * 8 + g) * 68 + ks + t4 + 4];
            mma_tf32(o[ni], af, bf);
        }
    }
    __syncthreads();    // everyone done reading Ks

    // O^T (tf32) -> Ks[dd][t]
#pragma unroll
    for (int ni = 0; ni < 8; ni++) {
        int dd = ni * 8 + 2 * t4;
        Ks[(dd + 0) * 68 + rA] = f2tf32(o[ni][0]);
        Ks[(dd + 1) * 68 + rA] = f2tf32(o[ni][1]);
        Ks[(dd + 0) * 68 + rB] = f2tf32(o[ni][2]);
        Ks[(dd + 1) * 68 + rB] = f2tf32(o[ni][3]);
    }
    __syncthreads();

    // Dump to g_o2[c][token-sigma], coalesced 16B chunks.
    const int bn = bh >> 3, h = bh & 7;
    uint32_t* go2 = (uint32_t*)g_o2;
    const int chunk = tid & 15;
    const int hi = (chunk >> 3) * 32, m8 = chunk & 7;
#pragma unroll
    for (int p = 0; p < 8; p++) {
        int row = (tid >> 4) + p * 8;     // channel-within-head 0..63
        uint4 w;
        w.x = Ks[row * 68 + hi + m8];
        w.y = Ks[row * 68 + hi + m8 + 8];
        w.z = Ks[row * 68 + hi + m8 + 16];
        w.w = Ks[row * 68 + hi + m8 + 24];
        *(uint4*)(go2 + (size_t)(h * 64 + row) * TOKENS + bn * 64 + chunk * 4) = w;
    }
}

// ---------------------------------------------------------------------------
// Kernel 3: output projection + bias + ReLU. grid (4, 1360): x = n-block (L2 reuse).
// ---------------------------------------------------------------------------
__global__ __launch_bounds__(256, 2)
void out_kernel(const float* __restrict__ bo, float* __restrict__ out)
{
    extern __shared__ float sm[];
    __shared__ int outOff[128];

    const int tid = threadIdx.x;
    const int m0  = blockIdx.y * 128;
    const int r0  = blockIdx.x * 128;

    if (tid < 128) {
        int token = m0 + tid;
        int bn = token >> 6;
        int b = bn / NPOS, n = bn % NPOS;
        outOff[tid] = (b * COUT * NPOS + n) * TT + (token & 63);
    }

    int kA[4], dstA[4], gB[4], dstB[4];
#pragma unroll
    for (int j = 0; j < 4; j++) {
        int cidx = tid + j * 256;
        kA[j] = cidx >> 5;
        int tc = cidx & 31;
        dstA[j] = kA[j] * SA + tc * 4;
        kA[j] = kA[j] * TOKENS + m0 + tc * 4;       // fold into single offset
        int nn = cidx >> 3, kc = cidx & 7;
        gB[j]   = ((3 * 512 + r0 + nn) * 16) * 32 + kc * 4;
        dstB[j] = nn * SB + kc * 4;
    }

    const int lane = tid & 31, wid = tid >> 5;
    const int wm = wid & 3, wn = wid >> 2;
    const int g = lane >> 2, t4 = lane & 3;
    const int mbase = wm * 32, nbase = wn * 64;

    float acc[2][8][4];
#pragma unroll
    for (int mi = 0; mi < 2; mi++)
#pragma unroll
        for (int ni = 0; ni < 8; ni++)
#pragma unroll
            for (int j = 0; j < 4; j++) acc[mi][ni][j] = 0.f;

    auto issue = [&](int stage, int kt) {
        float* As = sm + stage * STAGE;
        float* Bs = As + AW;
#pragma unroll
        for (int j = 0; j < 4; j++)
            cpasync16(As + dstA[j], g_o2 + kA[j] + kt * 32 * TOKENS);
#pragma unroll
        for (int j = 0; j < 4; j++)
            cpasync16(Bs + dstB[j], g_w + gB[j] + kt * 32);
    };

#pragma unroll
    for (int s = 0; s < 3; s++) { issue(s, s); CP_COMMIT(); }

    for (int it = 0; it < 16; it++) {
        CP_WAIT2();
        __syncthreads();
        const int buf = it % 3;
        const float* As = sm + buf * STAGE;
        const float* Bs = As + AW;
        mma_ktile(As, Bs, acc, mbase, nbase, g, t4);
        __syncthreads();
        int nx = it + 3;
        if (nx < 16) issue(buf, nx);
        CP_COMMIT();
    }

#pragma unroll
    for (int mi = 0; mi < 2; mi++) {
        int rloc = mbase + mi * 16 + g;
        int off0 = outOff[rloc];
        int off1 = outOff[rloc + 8];
#pragma unroll
        for (int ni = 0; ni < 8; ni++) {
            int jj = nbase + ni * 8 + 2 * t4;
            int o = r0 + jj;
            float b0 = bo[o], b1 = bo[o + 1];
            out[off0 + o * NTSTR]       = fmaxf(acc[mi][ni][0] + b0, 0.f);
            out[off0 + (o + 1) * NTSTR] = fmaxf(acc[mi][ni][1] + b1, 0.f);
            out[off1 + o * NTSTR]       = fmaxf(acc[mi][ni][2] + b0, 0.f);
            out[off1 + (o + 1) * NTSTR] = fmaxf(acc[mi][ni][3] + b1, 0.f);
        }
    }
}

// ---------------------------------------------------------------------------
extern "C" void kernel_launch(void* const* d_in, const int* in_sizes, int n_in,
                              void* d_out, int out_size)
{
    const float* x   = (const float*)d_in[0];
    const float* tem = (const float*)d_in[1];
    const float* Wq  = (const float*)d_in[2];
    const float* bq  = (const float*)d_in[3];
    const float* Wk  = (const float*)d_in[4];
    const float* bk  = (const float*)d_in[5];
    const float* Wv  = (const float*)d_in[6];
    const float* bv  = (const float*)d_in[7];
    const float* Wo  = (const float*)d_in[8];
    const float* bo  = (const float*)d_in[9];
    float* out = (float*)d_out;

    static bool attr_done = false;
    if (!attr_done) {
        cudaFuncSetAttribute(qkv_kernel, cudaFuncAttributeMaxDynamicSharedMemorySize, SMEM_BYTES);
        cudaFuncSetAttribute(out_kernel, cudaFuncAttributeMaxDynamicSharedMemorySize, SMEM_BYTES);
        attr_done = true;
    }

    cvt_x_kernel<<<512 * 16, 256>>>(x, tem);
    cvt_w_kernel<<<4096, 256>>>(Wq, Wk, Wv, Wo);   // FIX: full 1M elements

    dim3 g1(12, BN / 2);
    qkv_kernel<<<g1, 256, SMEM_BYTES>>>(bq, bk, bv);

    attn_kernel<<<BN * NHEAD, 128>>>();

    dim3 g3(4, BN / 2);
    out_kernel<<<g3, 256, SMEM_BYTES>>>(bo, out);
}